// round 1
// baseline (speedup 1.0000x reference)
#include <cuda_runtime.h>
#include <math.h>

// Problem constants
#define BATCH 2
#define SEQ   2048
#define DIM   1024
#define NH    16
#define HD    64
#define DFF_N 4096
#define ATT   256
#define MROWS (BATCH * SEQ)   // 4096

// ---------------- scratch (device globals; no allocation allowed) ----------
__device__ float g_q  [MROWS * DIM];
__device__ float g_k  [MROWS * DIM];
__device__ float g_v  [MROWS * DIM];
__device__ float g_ctx[MROWS * DIM];
__device__ float g_sa [MROWS * DIM];
__device__ float g_x1 [MROWS * DIM];
__device__ float g_h  [MROWS * DFF_N];
__device__ float g_y  [MROWS * DIM];

// ---------------- helpers ---------------------------------------------------
__device__ __forceinline__ float gelu_exact(float v) {
    return 0.5f * v * (1.0f + erff(v * 0.7071067811865476f));
}

// ---------------- tiled fp32 GEMM:  C = A[M,K] @ B[K,N] + bias (+res)(+gelu)
// BM=BN=64, BK=16, 256 threads, 4x4 register tile per thread.
// Requires M%64==0, N%64==0, K%16==0 (true for all shapes here).
// EPI: 0 = +bias, 1 = +bias+res, 2 = gelu(+bias)
template <int EPI>
__global__ void gemm_kernel(const float* __restrict__ A,
                            const float* __restrict__ B,
                            const float* __restrict__ bias,
                            const float* __restrict__ res,
                            float* __restrict__ C,
                            int M, int N, int Kd)
{
    __shared__ float As[16][64];   // transposed A tile: As[k][m]
    __shared__ float Bs[16][64];   // Bs[k][n]

    const int tid = threadIdx.x;          // 0..255
    const int tx  = tid & 15;             // 0..15
    const int ty  = tid >> 4;             // 0..15
    const int bm  = blockIdx.y * 64;
    const int bn  = blockIdx.x * 64;

    // per-thread load coordinates (4 contiguous floats each)
    const int aIdx = tid * 4;             // within 64x16 A tile
    const int ar   = aIdx >> 4;           // row in tile (0..63)
    const int ac   = aIdx & 15;           // col in tile {0,4,8,12}
    const int bIdx = tid * 4;             // within 16x64 B tile
    const int br   = bIdx >> 6;           // row (0..15)
    const int bc   = bIdx & 63;           // col {0,4,...,60}

    float acc[4][4] = {};

    for (int k0 = 0; k0 < Kd; k0 += 16) {
        float4 av = *(const float4*)&A[(size_t)(bm + ar) * Kd + k0 + ac];
        float4 bv = *(const float4*)&B[(size_t)(k0 + br) * N + bn + bc];
        __syncthreads();
        As[ac + 0][ar] = av.x;
        As[ac + 1][ar] = av.y;
        As[ac + 2][ar] = av.z;
        As[ac + 3][ar] = av.w;
        *(float4*)&Bs[br][bc] = bv;
        __syncthreads();

        #pragma unroll
        for (int kk = 0; kk < 16; kk++) {
            float4 a4 = *(const float4*)&As[kk][ty * 4];
            float4 b4 = *(const float4*)&Bs[kk][tx * 4];
            float a[4] = {a4.x, a4.y, a4.z, a4.w};
            float b[4] = {b4.x, b4.y, b4.z, b4.w};
            #pragma unroll
            for (int i = 0; i < 4; i++)
                #pragma unroll
                for (int j = 0; j < 4; j++)
                    acc[i][j] = fmaf(a[i], b[j], acc[i][j]);
        }
    }

    // epilogue (vectorized over the 4 contiguous output columns)
    #pragma unroll
    for (int i = 0; i < 4; i++) {
        int r = bm + ty * 4 + i;
        int c = bn + tx * 4;
        float4 bsv = *(const float4*)&bias[c];
        float o[4] = {acc[i][0] + bsv.x, acc[i][1] + bsv.y,
                      acc[i][2] + bsv.z, acc[i][3] + bsv.w};
        if (EPI == 1) {
            float4 rv = *(const float4*)&res[(size_t)r * N + c];
            o[0] += rv.x; o[1] += rv.y; o[2] += rv.z; o[3] += rv.w;
        }
        if (EPI == 2) {
            o[0] = gelu_exact(o[0]); o[1] = gelu_exact(o[1]);
            o[2] = gelu_exact(o[2]); o[3] = gelu_exact(o[3]);
        }
        float4 ov = {o[0], o[1], o[2], o[3]};
        *(float4*)&C[(size_t)r * N + c] = ov;
    }
}

// ---------------- banded attention (flash-style, one block per (b,h,query))
// 64 threads; thread t owns output dim t. Online softmax over band chunks.
__global__ void attn_kernel(const float* __restrict__ Q,
                            const float* __restrict__ Kmat,
                            const float* __restrict__ V,
                            float* __restrict__ O)
{
    const int i   = blockIdx.x;   // query position 0..SEQ-1
    const int h   = blockIdx.y;   // head
    const int b   = blockIdx.z;   // batch
    const int tid = threadIdx.x;  // 0..63

    __shared__ float qs[64];
    __shared__ float Ks[64][65];
    __shared__ float Vs[64][65];
    __shared__ float ssm[64];

    const float scale = 0.022097086912079608f; // 1/sqrt(2048) (seq-len scaling!)
    const size_t headbase = (size_t)b * SEQ * DIM + (size_t)h * HD;

    qs[tid] = Q[headbase + (size_t)i * DIM + tid];
    __syncthreads();

    const int jlo = max(i - ATT, 0);
    const int jhi = min(i + ATT, SEQ - 1);

    float m = -INFINITY, l = 0.f, acc = 0.f;

    for (int j0 = jlo; j0 <= jhi; j0 += 64) {
        const int nj = min(64, jhi - j0 + 1);

        // stage K/V tiles, coalesced over tid
        for (int r = 0; r < nj; r++) {
            size_t off = headbase + (size_t)(j0 + r) * DIM + tid;
            Ks[r][tid] = Kmat[off];
            Vs[r][tid] = V[off];
        }
        __syncthreads();

        float s;
        if (tid < nj) {
            s = 0.f;
            #pragma unroll 8
            for (int d = 0; d < 64; d++) s = fmaf(qs[d], Ks[tid][d], s);
            s *= scale;
        } else {
            s = -INFINITY;
        }
        ssm[tid] = s;
        __syncthreads();

        float cmax = -INFINITY;
        for (int t = 0; t < nj; t++) cmax = fmaxf(cmax, ssm[t]);
        const float nm = fmaxf(m, cmax);
        const float sc = (m == -INFINITY) ? 0.f : __expf(m - nm);
        acc *= sc;
        l   *= sc;
        float lsum = 0.f;
        for (int t = 0; t < nj; t++) {
            float p = __expf(ssm[t] - nm);
            lsum += p;
            acc = fmaf(p, Vs[t][tid], acc);
        }
        l += lsum;
        m = nm;
        __syncthreads();
    }

    O[headbase + (size_t)i * DIM + tid] = acc / l;
}

// ---------------- LayerNorm: one block (256 thr) per row of [MROWS, DIM]
__global__ void ln_kernel(const float* __restrict__ X,
                          const float* __restrict__ g,
                          const float* __restrict__ bb,
                          float* __restrict__ Y)
{
    const int row = blockIdx.x;
    const int tid = threadIdx.x;
    const float* x = X + (size_t)row * DIM;
    __shared__ float red[256];

    float s = 0.f, s2 = 0.f;
    for (int c = tid; c < DIM; c += 256) {
        float v = x[c];
        s  += v;
        s2 += v * v;
    }

    red[tid] = s; __syncthreads();
    for (int o = 128; o > 0; o >>= 1) {
        if (tid < o) red[tid] += red[tid + o];
        __syncthreads();
    }
    const float mu = red[0] * (1.0f / DIM);
    __syncthreads();

    red[tid] = s2; __syncthreads();
    for (int o = 128; o > 0; o >>= 1) {
        if (tid < o) red[tid] += red[tid + o];
        __syncthreads();
    }
    const float var = red[0] * (1.0f / DIM) - mu * mu;
    const float inv = rsqrtf(var + 1e-5f);

    for (int c = tid; c < DIM; c += 256) {
        Y[(size_t)row * DIM + c] = (x[c] - mu) * inv * g[c] + bb[c];
    }
}

// ---------------- launch ----------------------------------------------------
extern "C" void kernel_launch(void* const* d_in, const int* in_sizes, int n_in,
                              void* d_out, int out_size)
{
    const float* x    = (const float*)d_in[0];
    const float* Wq   = (const float*)d_in[1];
    const float* bq   = (const float*)d_in[2];
    const float* Wk   = (const float*)d_in[3];
    const float* bk   = (const float*)d_in[4];
    const float* Wv   = (const float*)d_in[5];
    const float* bv   = (const float*)d_in[6];
    const float* Wo   = (const float*)d_in[7];
    const float* bo   = (const float*)d_in[8];
    const float* W1   = (const float*)d_in[9];
    const float* b1   = (const float*)d_in[10];
    const float* W2   = (const float*)d_in[11];
    const float* b2   = (const float*)d_in[12];
    const float* ln1g = (const float*)d_in[13];
    const float* ln1b = (const float*)d_in[14];
    const float* ln2g = (const float*)d_in[15];
    const float* ln2b = (const float*)d_in[16];
    float* out = (float*)d_out;

    float *q, *k, *v, *ctx, *sa, *x1, *hh, *y;
    cudaGetSymbolAddress((void**)&q,   g_q);
    cudaGetSymbolAddress((void**)&k,   g_k);
    cudaGetSymbolAddress((void**)&v,   g_v);
    cudaGetSymbolAddress((void**)&ctx, g_ctx);
    cudaGetSymbolAddress((void**)&sa,  g_sa);
    cudaGetSymbolAddress((void**)&x1,  g_x1);
    cudaGetSymbolAddress((void**)&hh,  g_h);
    cudaGetSymbolAddress((void**)&y,   g_y);

    dim3 blk(256);
    // QKV projections
    gemm_kernel<0><<<dim3(DIM / 64,  MROWS / 64), blk>>>(x, Wq, bq, nullptr, q, MROWS, DIM, DIM);
    gemm_kernel<0><<<dim3(DIM / 64,  MROWS / 64), blk>>>(x, Wk, bk, nullptr, k, MROWS, DIM, DIM);
    gemm_kernel<0><<<dim3(DIM / 64,  MROWS / 64), blk>>>(x, Wv, bv, nullptr, v, MROWS, DIM, DIM);

    // banded attention
    attn_kernel<<<dim3(SEQ, NH, BATCH), 64>>>(q, k, v, ctx);

    // out projection + residual(x)
    gemm_kernel<1><<<dim3(DIM / 64,  MROWS / 64), blk>>>(ctx, Wo, bo, x, sa, MROWS, DIM, DIM);
    // LN1
    ln_kernel<<<MROWS, 256>>>(sa, ln1g, ln1b, x1);

    // FFN
    gemm_kernel<2><<<dim3(DFF_N / 64, MROWS / 64), blk>>>(x1, W1, b1, nullptr, hh, MROWS, DFF_N, DIM);
    gemm_kernel<1><<<dim3(DIM / 64,  MROWS / 64), blk>>>(hh, W2, b2, x1, y, MROWS, DIM, DFF_N);

    // LN2 -> output
    ln_kernel<<<MROWS, 256>>>(y, ln2g, ln2b, out);
}

// round 2
// speedup vs baseline: 2.8524x; 2.8524x over previous
#include <cuda_runtime.h>
#include <math.h>

// Problem constants
#define BATCH 2
#define SEQ   2048
#define DIM   1024
#define NH    16
#define HD    64
#define DFF_N 4096
#define ATT   256
#define MROWS (BATCH * SEQ)   // 4096

// ---------------- scratch (device globals; no allocation allowed) ----------
__device__ float g_q  [MROWS * DIM];
__device__ float g_k  [MROWS * DIM];
__device__ float g_v  [MROWS * DIM];
__device__ float g_ctx[MROWS * DIM];
__device__ float g_sa [MROWS * DIM];
__device__ float g_x1 [MROWS * DIM];
__device__ float g_h  [MROWS * DFF_N];
__device__ float g_y  [MROWS * DIM];

// ---------------- helpers ---------------------------------------------------
__device__ __forceinline__ float gelu_exact(float v) {
    return 0.5f * v * (1.0f + erff(v * 0.7071067811865476f));
}

// =====================================================================
// GEMM: C = A[M,K] @ B[K,N] (+bias)(+res)(+gelu)
// BM=BN=128, BK=8, 256 threads, 8x8 per thread (split 4+4 fragments),
// ping-pong double-buffered smem, conflict-free LDS.
// EPI: 0 = +bias, 1 = +bias+res, 2 = gelu(+bias)
// Requires M%128==0, N%128==0, K%8==0.
// =====================================================================
template <int EPI>
__global__ __launch_bounds__(256, 2)
void gemm128(const float* __restrict__ A,
             const float* __restrict__ B,
             const float* __restrict__ bias,
             const float* __restrict__ res,
             float* __restrict__ C,
             int M, int N, int Kd)
{
    __shared__ float As[2][8][132];   // transposed A tile, padded
    __shared__ float Bs[2][8][128];

    const int tid = threadIdx.x;          // 0..255
    const int tx  = tid & 15;             // 0..15
    const int ty  = tid >> 4;             // 0..15
    const int bm  = blockIdx.y * 128;
    const int bn  = blockIdx.x * 128;

    // A tile (128 rows x 8 cols): one float4 per thread
    const int arow = tid >> 1;            // 0..127
    const int acol = (tid & 1) * 4;       // 0 or 4
    // B tile (8 rows x 128 cols): one float4 per thread
    const int brow = tid >> 5;            // 0..7
    const int bcol = (tid & 31) * 4;      // 0..124

    const float* Aptr = A + (size_t)(bm + arow) * Kd + acol;
    const float* Bptr = B + (size_t)brow * N + bn + bcol;

    float4 aReg = *(const float4*)Aptr;
    float4 bReg = *(const float4*)Bptr;

    float acc[8][8];
    #pragma unroll
    for (int i = 0; i < 8; i++)
        #pragma unroll
        for (int j = 0; j < 8; j++) acc[i][j] = 0.f;

    // store first tile
    As[0][acol + 0][arow] = aReg.x;
    As[0][acol + 1][arow] = aReg.y;
    As[0][acol + 2][arow] = aReg.z;
    As[0][acol + 3][arow] = aReg.w;
    *(float4*)&Bs[0][brow][bcol] = bReg;
    __syncthreads();

    const int T = Kd >> 3;
    int p = 0;
    for (int t = 0; t < T; t++) {
        if (t + 1 < T) {
            aReg = *(const float4*)(Aptr + (t + 1) * 8);
            bReg = *(const float4*)(Bptr + (size_t)(t + 1) * 8 * N);
        }
        #pragma unroll
        for (int kk = 0; kk < 8; kk++) {
            float4 a0 = *(const float4*)&As[p][kk][ty * 4];
            float4 a1 = *(const float4*)&As[p][kk][64 + ty * 4];
            float4 b0 = *(const float4*)&Bs[p][kk][tx * 4];
            float4 b1 = *(const float4*)&Bs[p][kk][64 + tx * 4];
            float a[8] = {a0.x, a0.y, a0.z, a0.w, a1.x, a1.y, a1.z, a1.w};
            float b[8] = {b0.x, b0.y, b0.z, b0.w, b1.x, b1.y, b1.z, b1.w};
            #pragma unroll
            for (int i = 0; i < 8; i++)
                #pragma unroll
                for (int j = 0; j < 8; j++)
                    acc[i][j] = fmaf(a[i], b[j], acc[i][j]);
        }
        if (t + 1 < T) {
            int np = p ^ 1;
            As[np][acol + 0][arow] = aReg.x;
            As[np][acol + 1][arow] = aReg.y;
            As[np][acol + 2][arow] = aReg.z;
            As[np][acol + 3][arow] = aReg.w;
            *(float4*)&Bs[np][brow][bcol] = bReg;
            __syncthreads();
            p = np;
        }
    }

    // epilogue: rows {ty*4+i, 64+ty*4+i}, cols {tx*4.., 64+tx*4..}
    #pragma unroll
    for (int ih = 0; ih < 2; ih++) {
        #pragma unroll
        for (int i = 0; i < 4; i++) {
            int r = bm + ih * 64 + ty * 4 + i;
            #pragma unroll
            for (int jh = 0; jh < 2; jh++) {
                int c = bn + jh * 64 + tx * 4;
                float4 bsv = *(const float4*)&bias[c];
                float o[4];
                #pragma unroll
                for (int j = 0; j < 4; j++)
                    o[j] = acc[ih * 4 + i][jh * 4 + j];
                o[0] += bsv.x; o[1] += bsv.y; o[2] += bsv.z; o[3] += bsv.w;
                if (EPI == 1) {
                    float4 rv = *(const float4*)&res[(size_t)r * N + c];
                    o[0] += rv.x; o[1] += rv.y; o[2] += rv.z; o[3] += rv.w;
                }
                if (EPI == 2) {
                    o[0] = gelu_exact(o[0]); o[1] = gelu_exact(o[1]);
                    o[2] = gelu_exact(o[2]); o[3] = gelu_exact(o[3]);
                }
                float4 ov = {o[0], o[1], o[2], o[3]};
                *(float4*)&C[(size_t)r * N + c] = ov;
            }
        }
    }
}

// =====================================================================
// Banded attention, 64-query tiles. One block per (qtile, head, batch).
// 256 threads (16x16), 4x4 register tiles for both S=Q@K^T and O=P@V.
// Band geometry guarantees every 64-key chunk is full. Smem: Qt+Kt+Vs
// = 48KB; the P tile reuses the Kt buffer.
// =====================================================================
#define NEGBIG (-1e30f)

// XOR swizzle: column q stored at q ^ (4*((d>>2)&7))
__device__ __forceinline__ int swz(int d, int q) {
    return q ^ (((d >> 2) & 7) << 2);
}

__global__ __launch_bounds__(256, 2)
void attn_kernel(const float* __restrict__ Q,
                 const float* __restrict__ Kmat,
                 const float* __restrict__ V,
                 float* __restrict__ O)
{
    __shared__ float Qt[64][64];   // Qt[d][q] (swizzled)
    __shared__ float Kt[64][64];   // Kt[d][k] (swizzled); reused as Ps[k][q]
    __shared__ float Vs[64][64];   // Vs[k][d] natural

    const int tid = threadIdx.x;
    const int tx  = tid & 15;
    const int ty  = tid >> 4;
    const int q0  = blockIdx.x * 64;
    const int h   = blockIdx.y;
    const int b   = blockIdx.z;

    const float scale = 0.022097086912079608f; // 1/sqrt(2048)
    const size_t headbase = (size_t)b * SEQ * DIM + (size_t)h * HD;

    // ---- stage Q tile (transposed + swizzled) ----
    {
        const int lq = tid >> 4;            // 0..15 (step by 16)
        const int d0 = (tid & 15) * 4;
        const int c  = ((d0 >> 2) & 7) << 2;
        #pragma unroll
        for (int r = 0; r < 4; r++) {
            int q = r * 16 + lq;
            float4 v4 = *(const float4*)&Q[headbase + (size_t)(q0 + q) * DIM + d0];
            Qt[d0 + 0][q ^ c] = v4.x;
            Qt[d0 + 1][q ^ c] = v4.y;
            Qt[d0 + 2][q ^ c] = v4.z;
            Qt[d0 + 3][q ^ c] = v4.w;
        }
    }

    const int jlo = max(q0 - ATT, 0);
    const int jhi = min(q0 + 63 + ATT, SEQ - 1);

    float acc[4][4];
    #pragma unroll
    for (int i = 0; i < 4; i++)
        #pragma unroll
        for (int j = 0; j < 4; j++) acc[i][j] = 0.f;
    float mrow[4] = {NEGBIG, NEGBIG, NEGBIG, NEGBIG};
    float lrow[4] = {0.f, 0.f, 0.f, 0.f};

    for (int j0 = jlo; j0 <= jhi; j0 += 64) {
        __syncthreads();   // previous chunk's Kt(P)/Vs reads done
        // ---- stage K (transposed+swizzled) and V (natural) ----
        {
            const int lk = tid >> 4;
            const int d0 = (tid & 15) * 4;
            const int c  = ((d0 >> 2) & 7) << 2;
            #pragma unroll
            for (int r = 0; r < 4; r++) {
                int k = r * 16 + lk;
                size_t off = headbase + (size_t)(j0 + k) * DIM + d0;
                float4 kv = *(const float4*)&Kmat[off];
                Kt[d0 + 0][k ^ c] = kv.x;
                Kt[d0 + 1][k ^ c] = kv.y;
                Kt[d0 + 2][k ^ c] = kv.z;
                Kt[d0 + 3][k ^ c] = kv.w;
                *(float4*)&Vs[k][d0] = *(const float4*)&V[off];
            }
        }
        __syncthreads();

        // ---- S = Q @ K^T (4x4 per thread) ----
        float s[4][4];
        #pragma unroll
        for (int i = 0; i < 4; i++)
            #pragma unroll
            for (int j = 0; j < 4; j++) s[i][j] = 0.f;
        #pragma unroll 8
        for (int kk = 0; kk < 64; kk++) {
            const int c = ((kk >> 2) & 7) << 2;
            float4 a4 = *(const float4*)&Qt[kk][(ty * 4) ^ c];
            float4 b4 = *(const float4*)&Kt[kk][(tx * 4) ^ c];
            float a[4] = {a4.x, a4.y, a4.z, a4.w};
            float bb[4] = {b4.x, b4.y, b4.z, b4.w};
            #pragma unroll
            for (int i = 0; i < 4; i++)
                #pragma unroll
                for (int j = 0; j < 4; j++)
                    s[i][j] = fmaf(a[i], bb[j], s[i][j]);
        }

        // ---- scale + band mask ----
        #pragma unroll
        for (int i = 0; i < 4; i++) {
            int q = q0 + ty * 4 + i;
            #pragma unroll
            for (int j = 0; j < 4; j++) {
                int k = j0 + tx * 4 + j;
                int d = q - k;
                if (d > ATT || d < -ATT) s[i][j] = NEGBIG;
                else                      s[i][j] *= scale;
            }
        }

        // ---- online softmax update (reduce over 16 tx lanes) ----
        float alpha[4];
        #pragma unroll
        for (int i = 0; i < 4; i++) {
            float cm = fmaxf(fmaxf(s[i][0], s[i][1]), fmaxf(s[i][2], s[i][3]));
            cm = fmaxf(cm, __shfl_xor_sync(0xffffffffu, cm, 1));
            cm = fmaxf(cm, __shfl_xor_sync(0xffffffffu, cm, 2));
            cm = fmaxf(cm, __shfl_xor_sync(0xffffffffu, cm, 4));
            cm = fmaxf(cm, __shfl_xor_sync(0xffffffffu, cm, 8));
            float mn = fmaxf(mrow[i], cm);
            alpha[i] = __expf(mrow[i] - mn);       // 0 if mrow≪mn; 1 if equal
            float psum = 0.f;
            #pragma unroll
            for (int j = 0; j < 4; j++) {
                s[i][j] = __expf(s[i][j] - mn);
                psum += s[i][j];
            }
            psum += __shfl_xor_sync(0xffffffffu, psum, 1);
            psum += __shfl_xor_sync(0xffffffffu, psum, 2);
            psum += __shfl_xor_sync(0xffffffffu, psum, 4);
            psum += __shfl_xor_sync(0xffffffffu, psum, 8);
            lrow[i] = lrow[i] * alpha[i] + psum;
            mrow[i] = mn;
            #pragma unroll
            for (int j = 0; j < 4; j++) acc[i][j] *= alpha[i];
        }

        __syncthreads();   // everyone done reading Kt

        // ---- write P into Kt buffer as Ps[k][q] (swizzled) ----
        #pragma unroll
        for (int j = 0; j < 4; j++) {
            int k = tx * 4 + j;
            int c = ((k >> 2) & 7) << 2;
            #pragma unroll
            for (int i = 0; i < 4; i++)
                Kt[k][(ty * 4 + i) ^ c] = s[i][j];
        }
        __syncthreads();

        // ---- O += P @ V ----
        #pragma unroll 8
        for (int kk = 0; kk < 64; kk++) {
            const int c = ((kk >> 2) & 7) << 2;
            float4 a4 = *(const float4*)&Kt[kk][(ty * 4) ^ c];   // P[q][kk]
            float4 b4 = *(const float4*)&Vs[kk][tx * 4];
            float a[4] = {a4.x, a4.y, a4.z, a4.w};
            float bb[4] = {b4.x, b4.y, b4.z, b4.w};
            #pragma unroll
            for (int i = 0; i < 4; i++)
                #pragma unroll
                for (int j = 0; j < 4; j++)
                    acc[i][j] = fmaf(a[i], bb[j], acc[i][j]);
        }
    }

    // ---- write output ----
    #pragma unroll
    for (int i = 0; i < 4; i++) {
        float inv = 1.0f / lrow[i];
        int q = q0 + ty * 4 + i;
        float4 ov = {acc[i][0] * inv, acc[i][1] * inv,
                     acc[i][2] * inv, acc[i][3] * inv};
        *(float4*)&O[headbase + (size_t)q * DIM + tx * 4] = ov;
    }
}

// ---------------- LayerNorm: one block (256 thr) per row of [MROWS, DIM]
__global__ void ln_kernel(const float* __restrict__ X,
                          const float* __restrict__ g,
                          const float* __restrict__ bb,
                          float* __restrict__ Y)
{
    const int row = blockIdx.x;
    const int tid = threadIdx.x;
    const float* x = X + (size_t)row * DIM;
    __shared__ float red[256];

    float s = 0.f, s2 = 0.f;
    for (int c = tid; c < DIM; c += 256) {
        float v = x[c];
        s  += v;
        s2 += v * v;
    }

    red[tid] = s; __syncthreads();
    for (int o = 128; o > 0; o >>= 1) {
        if (tid < o) red[tid] += red[tid + o];
        __syncthreads();
    }
    const float mu = red[0] * (1.0f / DIM);
    __syncthreads();

    red[tid] = s2; __syncthreads();
    for (int o = 128; o > 0; o >>= 1) {
        if (tid < o) red[tid] += red[tid + o];
        __syncthreads();
    }
    const float var = red[0] * (1.0f / DIM) - mu * mu;
    const float inv = rsqrtf(var + 1e-5f);

    for (int c = tid; c < DIM; c += 256) {
        Y[(size_t)row * DIM + c] = (x[c] - mu) * inv * g[c] + bb[c];
    }
}

// ---------------- launch ----------------------------------------------------
extern "C" void kernel_launch(void* const* d_in, const int* in_sizes, int n_in,
                              void* d_out, int out_size)
{
    const float* x    = (const float*)d_in[0];
    const float* Wq   = (const float*)d_in[1];
    const float* bq   = (const float*)d_in[2];
    const float* Wk   = (const float*)d_in[3];
    const float* bk   = (const float*)d_in[4];
    const float* Wv   = (const float*)d_in[5];
    const float* bv   = (const float*)d_in[6];
    const float* Wo   = (const float*)d_in[7];
    const float* bo   = (const float*)d_in[8];
    const float* W1   = (const float*)d_in[9];
    const float* b1   = (const float*)d_in[10];
    const float* W2   = (const float*)d_in[11];
    const float* b2   = (const float*)d_in[12];
    const float* ln1g = (const float*)d_in[13];
    const float* ln1b = (const float*)d_in[14];
    const float* ln2g = (const float*)d_in[15];
    const float* ln2b = (const float*)d_in[16];
    float* out = (float*)d_out;

    float *q, *k, *v, *ctx, *sa, *x1, *hh, *y;
    cudaGetSymbolAddress((void**)&q,   g_q);
    cudaGetSymbolAddress((void**)&k,   g_k);
    cudaGetSymbolAddress((void**)&v,   g_v);
    cudaGetSymbolAddress((void**)&ctx, g_ctx);
    cudaGetSymbolAddress((void**)&sa,  g_sa);
    cudaGetSymbolAddress((void**)&x1,  g_x1);
    cudaGetSymbolAddress((void**)&hh,  g_h);
    cudaGetSymbolAddress((void**)&y,   g_y);

    dim3 blk(256);
    // QKV projections
    gemm128<0><<<dim3(DIM / 128,  MROWS / 128), blk>>>(x, Wq, bq, nullptr, q, MROWS, DIM, DIM);
    gemm128<0><<<dim3(DIM / 128,  MROWS / 128), blk>>>(x, Wk, bk, nullptr, k, MROWS, DIM, DIM);
    gemm128<0><<<dim3(DIM / 128,  MROWS / 128), blk>>>(x, Wv, bv, nullptr, v, MROWS, DIM, DIM);

    // banded attention (64-query tiles)
    attn_kernel<<<dim3(SEQ / 64, NH, BATCH), blk>>>(q, k, v, ctx);

    // out projection + residual(x)
    gemm128<1><<<dim3(DIM / 128,  MROWS / 128), blk>>>(ctx, Wo, bo, x, sa, MROWS, DIM, DIM);
    // LN1
    ln_kernel<<<MROWS, 256>>>(sa, ln1g, ln1b, x1);

    // FFN
    gemm128<2><<<dim3(DFF_N / 128, MROWS / 128), blk>>>(x1, W1, b1, nullptr, hh, MROWS, DFF_N, DIM);
    gemm128<1><<<dim3(DIM / 128,  MROWS / 128), blk>>>(hh, W2, b2, x1, y, MROWS, DIM, DFF_N);

    // LN2 -> output
    ln_kernel<<<MROWS, 256>>>(y, ln2g, ln2b, out);
}